// round 14
// baseline (speedup 1.0000x reference)
#include <cuda_runtime.h>
#include <cuda_bf16.h>
#include <cuda_fp8.h>
#include <math.h>
#include <stdint.h>

// Problem constants
#define B_  2
#define L_  2048
#define C_  1024
#define H_  16
#define D_  64
#define BL_ (B_*L_)      // 4096
#define C3_ (3*C_)       // 3072
#define K_  1024

// ---------------- scratch (no allocation allowed) ----------------
__device__ float g_qkv[(size_t)BL_ * C3_];

__device__ __nv_bfloat16 g_x_hi [(size_t)BL_*C_];
__device__ uint8_t       g_x_h8 [(size_t)BL_*C_];
__device__ uint8_t       g_x_l8 [(size_t)BL_*C_];
__device__ __nv_bfloat16 g_wq_hi[(size_t)C3_*C_];
__device__ uint8_t       g_wq_h8[(size_t)C3_*C_];
__device__ uint8_t       g_wq_l8[(size_t)C3_*C_];

__device__ __nv_bfloat16 g_wo_hi[(size_t)C_*C_];
__device__ __nv_bfloat16 g_wo_lo[(size_t)C_*C_];
__device__ __nv_bfloat16 g_at_hi[(size_t)BL_*C_];
__device__ __nv_bfloat16 g_at_lo[(size_t)BL_*C_];

__device__ __nv_bfloat16 g_qh [(size_t)B_*H_*L_*D_];
__device__ __nv_bfloat16 g_ql [(size_t)B_*H_*L_*D_];
__device__ __nv_bfloat16 g_kh [(size_t)B_*H_*L_*D_];
__device__ __nv_bfloat16 g_kl [(size_t)B_*H_*L_*D_];
__device__ __nv_bfloat16 g_vth[(size_t)B_*H_*D_*L_];
__device__ __nv_bfloat16 g_vtl[(size_t)B_*H_*D_*L_];

// =================================================================
// helpers
// =================================================================
__device__ __forceinline__ uint32_t smem_u32(const void* p) {
    uint32_t a;
    asm("{ .reg .u64 t; cvta.to.shared.u64 t, %1; cvt.u32.u64 %0, t; }"
        : "=r"(a) : "l"(p));
    return a;
}
__device__ __forceinline__ void cpasync16(uint32_t dst, const void* src) {
    asm volatile("cp.async.cg.shared.global [%0], [%1], 16;"
                 :: "r"(dst), "l"(src));
}
__device__ __forceinline__ void ldm4(uint32_t* r, uint32_t addr) {
    asm volatile("ldmatrix.sync.aligned.m8n8.x4.shared.b16 {%0,%1,%2,%3}, [%4];"
                 : "=r"(r[0]), "=r"(r[1]), "=r"(r[2]), "=r"(r[3]) : "r"(addr));
}
__device__ __forceinline__ uint32_t lds32(uint32_t addr) {
    uint32_t v;
    asm volatile("ld.shared.u32 %0, [%1];" : "=r"(v) : "r"(addr));
    return v;
}
__device__ __forceinline__ void mma_bf16(float* c, const uint32_t* a,
                                         const uint32_t* b) {
    asm volatile(
        "mma.sync.aligned.m16n8k16.row.col.f32.bf16.bf16.f32 "
        "{%0,%1,%2,%3}, {%4,%5,%6,%7}, {%8,%9}, {%0,%1,%2,%3};"
        : "+f"(c[0]), "+f"(c[1]), "+f"(c[2]), "+f"(c[3])
        : "r"(a[0]), "r"(a[1]), "r"(a[2]), "r"(a[3]), "r"(b[0]), "r"(b[1]));
}
__device__ __forceinline__ void mma_fp8(float* c, const uint32_t* a,
                                        const uint32_t* b) {
    asm volatile(
        "mma.sync.aligned.m16n8k32.row.col.f32.e4m3.e4m3.f32 "
        "{%0,%1,%2,%3}, {%4,%5,%6,%7}, {%8,%9}, {%0,%1,%2,%3};"
        : "+f"(c[0]), "+f"(c[1]), "+f"(c[2]), "+f"(c[3])
        : "r"(a[0]), "r"(a[1]), "r"(a[2]), "r"(a[3]), "r"(b[0]), "r"(b[1]));
}
__device__ __forceinline__ float ex2f(float x) {
    float y;
    asm("ex2.approx.f32 %0, %1;" : "=f"(y) : "f"(x));
    return y;
}
__device__ __forceinline__ uint32_t pack_bf16x2(float e, float o) {
    uint32_t r;
    asm("cvt.rn.bf16x2.f32 %0, %1, %2;" : "=r"(r) : "f"(o), "f"(e));
    return r;
}
__device__ __forceinline__ void split_pack(float e, float o,
                                           uint32_t& hi, uint32_t& lo) {
    float he = __uint_as_float(__float_as_uint(e) & 0xffff0000u);
    float ho = __uint_as_float(__float_as_uint(o) & 0xffff0000u);
    hi = pack_bf16x2(he, ho);
    lo = pack_bf16x2(e - he, o - ho);
}

// =================================================================
// QKV GEMM: hybrid bf16(hi) + fp8(e4m3 cross terms) split.
//   C = Xhi*Whi  +  2^-12 * ( X8*(Wlo*2^12)_8  +  (Xlo*2^12)_8*W8 ) + bias
// CTA 128x64, BK=32, 128 threads / 4 warps (2m x 2n), warp 64x32.
// =================================================================
#define PITCH_B 80
#define PITCH8  48
#define AH_SZ   (128 * PITCH_B)   // 10240
#define BH_SZ   (64  * PITCH_B)   // 5120
#define A8_SZ   (128 * PITCH8)    // 6144
#define B8_SZ   (64  * PITCH8)    // 3072
// stage: Ahi | Bhi | Ah8 | Al8 | Bh8 | Bl8
#define OFF_BH  (AH_SZ)
#define OFF_AH8 (AH_SZ + BH_SZ)
#define OFF_AL8 (OFF_AH8 + A8_SZ)
#define OFF_BH8 (OFF_AL8 + A8_SZ)
#define OFF_BL8 (OFF_BH8 + B8_SZ)
#define STG8    (OFF_BL8 + B8_SZ)            // 33792
#define QKV_DSMEM (2 * STG8)                 // 67584
#define FP8_SCALE (1.0f / 4096.0f)

__global__ __launch_bounds__(128, 2)
void gemm_qkv_hyb(const __nv_bfloat16* __restrict__ Ahi,
                  const uint8_t* __restrict__ A8,
                  const uint8_t* __restrict__ Al8,
                  const __nv_bfloat16* __restrict__ Bhi,
                  const uint8_t* __restrict__ B8,
                  const uint8_t* __restrict__ Bl8,
                  const float* __restrict__ bias,
                  float* __restrict__ Cout, int Nt)
{
    extern __shared__ char dsm[];
    const uint32_t sb = smem_u32(dsm);

    const int tid  = threadIdx.x;
    const int wid  = tid >> 5;
    const int lane = tid & 31;
    const int wm   = wid >> 1;        // 0..1 -> 64-row slab
    const int wn   = wid & 1;         // 0..1 -> 32-col slab
    const int row0 = blockIdx.y << 7;
    const int col0 = blockIdx.x << 6;

    auto load_chunk = [&](int c, int s) {
        const uint32_t st = sb + s * STG8;
        const int kb = c * 32;
        // Ahi: 128 rows x 32 bf16 = 512 x16B
#pragma unroll
        for (int t = 0; t < 4; t++) {
            int lin = tid + t * 128;
            int r = lin >> 2, q = lin & 3;
            cpasync16(st + (uint32_t)(r * PITCH_B + q * 16),
                      Ahi + (size_t)(row0 + r) * K_ + kb + q * 8);
        }
        // Bhi: 64 rows x 32 bf16 = 256 x16B
#pragma unroll
        for (int t = 0; t < 2; t++) {
            int lin = tid + t * 128;
            int r = lin >> 2, q = lin & 3;
            cpasync16(st + OFF_BH + (uint32_t)(r * PITCH_B + q * 16),
                      Bhi + (size_t)(col0 + r) * K_ + kb + q * 8);
        }
        // Ah8 / Al8: 128 rows x 32 B = 256 x16B each
#pragma unroll
        for (int t = 0; t < 2; t++) {
            int lin = tid + t * 128;
            int r = lin >> 1, hf = lin & 1;
            uint32_t so = (uint32_t)(r * PITCH8 + hf * 16);
            size_t go = (size_t)(row0 + r) * K_ + kb + hf * 16;
            cpasync16(st + OFF_AH8 + so, A8 + go);
            cpasync16(st + OFF_AL8 + so, Al8 + go);
        }
        // Bh8 / Bl8: 64 rows x 32 B = 128 x16B each
        {
            int r = tid >> 1, hf = tid & 1;
            uint32_t so = (uint32_t)(r * PITCH8 + hf * 16);
            size_t go = (size_t)(col0 + r) * K_ + kb + hf * 16;
            cpasync16(st + OFF_BH8 + so, B8 + go);
            cpasync16(st + OFF_BL8 + so, Bl8 + go);
        }
        asm volatile("cp.async.commit_group;" ::: "memory");
    };

    float acc[4][4][4];   // bf16 hi*hi
    float ac2[4][4][4];   // fp8 cross terms (scaled 2^12)
#pragma unroll
    for (int i = 0; i < 4; i++)
#pragma unroll
        for (int j = 0; j < 4; j++)
#pragma unroll
            for (int t = 0; t < 4; t++) { acc[i][j][t] = 0.f; ac2[i][j][t] = 0.f; }

    load_chunk(0, 0);
    load_chunk(1, 1);

    const int NCH = K_ / 32;
    const int rlA = lane & 15;
    const int csA = (lane >> 4) << 3;
    const int rlB = (lane & 7) + ((lane >> 4) << 3);
    const int csB = lane & 8;
    // fp8 per-lane offsets
    const int r8  = lane >> 2;        // row/col within 8-group / 16-tile
    const int k8  = (lane & 3) * 4;   // byte offset in k

    for (int c = 0; c < NCH; c++) {
        const int s = c & 1;
        if (c == NCH - 1)
            asm volatile("cp.async.wait_group 0;" ::: "memory");
        else
            asm volatile("cp.async.wait_group 1;" ::: "memory");
        __syncthreads();

        const uint32_t st = sb + s * STG8;

        // ---- fp8 fragment loads (issue early; latency hidden by HH) ----
        uint32_t ah8[4][4], al8[4][4];   // A frags m16n8k32: 4 regs each
#pragma unroll
        for (int mt = 0; mt < 4; mt++) {
            uint32_t base = st + (uint32_t)((wm * 64 + mt * 16 + r8) * PITCH8 + k8);
            ah8[mt][0] = lds32(OFF_AH8 + base);
            ah8[mt][1] = lds32(OFF_AH8 + base + 8 * PITCH8);
            ah8[mt][2] = lds32(OFF_AH8 + base + 16);
            ah8[mt][3] = lds32(OFF_AH8 + base + 8 * PITCH8 + 16);
            al8[mt][0] = lds32(OFF_AL8 + base);
            al8[mt][1] = lds32(OFF_AL8 + base + 8 * PITCH8);
            al8[mt][2] = lds32(OFF_AL8 + base + 16);
            al8[mt][3] = lds32(OFF_AL8 + base + 8 * PITCH8 + 16);
        }
        uint32_t bh8[4][2], bl8[4][2];   // B frags: 4 n8-groups x 2 regs
#pragma unroll
        for (int nt = 0; nt < 4; nt++) {
            uint32_t base = st + (uint32_t)((wn * 32 + nt * 8 + r8) * PITCH8 + k8);
            bh8[nt][0] = lds32(OFF_BH8 + base);
            bh8[nt][1] = lds32(OFF_BH8 + base + 16);
            bl8[nt][0] = lds32(OFF_BL8 + base);
            bl8[nt][1] = lds32(OFF_BL8 + base + 16);
        }

        // ---- bf16 hi*hi phase ----
#pragma unroll
        for (int kk = 0; kk < 32; kk += 16) {
            uint32_t aH[4][4], bH[2][4];
#pragma unroll
            for (int mt = 0; mt < 4; mt++) {
                uint32_t ad = st + (uint32_t)((wm * 64 + mt * 16 + rlA) * PITCH_B
                                              + (kk + csA) * 2);
                ldm4(aH[mt], ad);
            }
#pragma unroll
            for (int ntp = 0; ntp < 2; ntp++) {
                uint32_t bd = st + OFF_BH
                            + (uint32_t)((wn * 32 + ntp * 16 + rlB) * PITCH_B
                                         + (kk + csB) * 2);
                ldm4(bH[ntp], bd);
            }
#pragma unroll
            for (int mt = 0; mt < 4; mt++)
#pragma unroll
                for (int ntp = 0; ntp < 2; ntp++) {
                    mma_bf16(acc[mt][2 * ntp],     aH[mt], bH[ntp]);
                    mma_bf16(acc[mt][2 * ntp + 1], aH[mt], bH[ntp] + 2);
                }
        }

        // ---- fp8 cross-term phase (term-major, reuse distance 16) ----
#pragma unroll
        for (int mt = 0; mt < 4; mt++)
#pragma unroll
            for (int nt = 0; nt < 4; nt++)
                mma_fp8(ac2[mt][nt], ah8[mt], bl8[nt]);
#pragma unroll
        for (int mt = 0; mt < 4; mt++)
#pragma unroll
            for (int nt = 0; nt < 4; nt++)
                mma_fp8(ac2[mt][nt], al8[mt], bh8[nt]);

        __syncthreads();
        if (c + 2 < NCH) load_chunk(c + 2, s);
    }

    // Epilogue: combine
#pragma unroll
    for (int mt = 0; mt < 4; mt++) {
#pragma unroll
        for (int nt = 0; nt < 4; nt++) {
            int row = row0 + wm * 64 + mt * 16 + (lane >> 2);
            int col = col0 + wn * 32 + nt * 8 + (lane & 3) * 2;
            float bx = bias[col], by = bias[col + 1];
            float2 v0 = {acc[mt][nt][0] + ac2[mt][nt][0] * FP8_SCALE + bx,
                         acc[mt][nt][1] + ac2[mt][nt][1] * FP8_SCALE + by};
            float2 v1 = {acc[mt][nt][2] + ac2[mt][nt][2] * FP8_SCALE + bx,
                         acc[mt][nt][3] + ac2[mt][nt][3] * FP8_SCALE + by};
            *reinterpret_cast<float2*>(Cout + (size_t)row * Nt + col) = v0;
            *reinterpret_cast<float2*>(Cout + (size_t)(row + 8) * Nt + col) = v1;
        }
    }
}

// =================================================================
// Split-bf16 mma.sync GEMM (R13, kept for out-proj, NTP=4)
// =================================================================
#define MAT_A   (128 * PITCH_B)

template<int NTP>
__global__ __launch_bounds__(128, 1)
void gemm_mma(const __nv_bfloat16* __restrict__ Ahi,
              const __nv_bfloat16* __restrict__ Alo,
              const __nv_bfloat16* __restrict__ Bhi,
              const __nv_bfloat16* __restrict__ Blo,
              const float* __restrict__ bias,
              float* __restrict__ Cout, int Nt)
{
    constexpr int NTILE = 32 * NTP;
    constexpr int MAT_B = NTILE * PITCH_B;
    constexpr int STG   = 2 * MAT_A + 2 * MAT_B;

    extern __shared__ char dsm[];
    const uint32_t sb = smem_u32(dsm);

    const int tid  = threadIdx.x;
    const int wid  = tid >> 5;
    const int lane = tid & 31;
    const int wm   = wid >> 1;
    const int wn   = wid & 1;
    const int row0 = blockIdx.y << 7;
    const int col0 = blockIdx.x * NTILE;

    auto load_chunk = [&](int c, int s) {
        const uint32_t st = sb + s * STG;
        const int kb = c * 32;
#pragma unroll
        for (int t = 0; t < 4; t++) {
            int lin = tid + t * 128;
            int r = lin >> 2, q = lin & 3;
            uint32_t so = (uint32_t)(r * PITCH_B + q * 16);
            size_t go = (size_t)(row0 + r) * K_ + kb + q * 8;
            cpasync16(st + so,         Ahi + go);
            cpasync16(st + MAT_A + so, Alo + go);
        }
#pragma unroll
        for (int t = 0; t < NTP; t++) {
            int lin = tid + t * 128;
            int r = lin >> 2, q = lin & 3;
            uint32_t so = (uint32_t)(r * PITCH_B + q * 16);
            size_t go = (size_t)(col0 + r) * K_ + kb + q * 8;
            cpasync16(st + 2 * MAT_A + so,         Bhi + go);
            cpasync16(st + 2 * MAT_A + MAT_B + so, Blo + go);
        }
        asm volatile("cp.async.commit_group;" ::: "memory");
    };

    float acc[4][2 * NTP][4];
#pragma unroll
    for (int i = 0; i < 4; i++)
#pragma unroll
        for (int j = 0; j < 2 * NTP; j++)
#pragma unroll
            for (int t = 0; t < 4; t++) acc[i][j][t] = 0.f;

    load_chunk(0, 0);
    load_chunk(1, 1);

    const int NCH = K_ / 32;
    const int rlA = lane & 15;
    const int csA = (lane >> 4) << 3;
    const int rlB = (lane & 7) + ((lane >> 4) << 3);
    const int csB = lane & 8;

    for (int c = 0; c < NCH; c++) {
        const int s = c & 1;
        if (c == NCH - 1)
            asm volatile("cp.async.wait_group 0;" ::: "memory");
        else
            asm volatile("cp.async.wait_group 1;" ::: "memory");
        __syncthreads();

        const uint32_t st = sb + s * STG;
#pragma unroll
        for (int kk = 0; kk < 32; kk += 16) {
            uint32_t aH[4][4], aL[4][4], bH[NTP][4], bL[NTP][4];
#pragma unroll
            for (int mt = 0; mt < 4; mt++) {
                uint32_t ad = st + (uint32_t)((wm * 64 + mt * 16 + rlA) * PITCH_B
                                              + (kk + csA) * 2);
                ldm4(aH[mt], ad);
                ldm4(aL[mt], ad + MAT_A);
            }
#pragma unroll
            for (int ntp = 0; ntp < NTP; ntp++) {
                uint32_t bd = st + 2 * MAT_A
                            + (uint32_t)((wn * (16 * NTP) + ntp * 16 + rlB) * PITCH_B
                                         + (kk + csB) * 2);
                ldm4(bH[ntp], bd);
                ldm4(bL[ntp], bd + MAT_B);
            }
#pragma unroll
            for (int mt = 0; mt < 4; mt++)
#pragma unroll
                for (int ntp = 0; ntp < NTP; ntp++) {
                    mma_bf16(acc[mt][2 * ntp],     aH[mt], bH[ntp]);
                    mma_bf16(acc[mt][2 * ntp + 1], aH[mt], bH[ntp] + 2);
                }
#pragma unroll
            for (int mt = 0; mt < 4; mt++)
#pragma unroll
                for (int ntp = 0; ntp < NTP; ntp++) {
                    mma_bf16(acc[mt][2 * ntp],     aH[mt], bL[ntp]);
                    mma_bf16(acc[mt][2 * ntp + 1], aH[mt], bL[ntp] + 2);
                }
#pragma unroll
            for (int mt = 0; mt < 4; mt++)
#pragma unroll
                for (int ntp = 0; ntp < NTP; ntp++) {
                    mma_bf16(acc[mt][2 * ntp],     aL[mt], bH[ntp]);
                    mma_bf16(acc[mt][2 * ntp + 1], aL[mt], bH[ntp] + 2);
                }
        }
        __syncthreads();
        if (c + 2 < NCH) load_chunk(c + 2, s);
    }

#pragma unroll
    for (int mt = 0; mt < 4; mt++) {
#pragma unroll
        for (int nt = 0; nt < 2 * NTP; nt++) {
            int row = row0 + wm * 64 + mt * 16 + (lane >> 2);
            int col = col0 + wn * (16 * NTP) + nt * 8 + (lane & 3) * 2;
            float bx = bias[col], by = bias[col + 1];
            float2 v0 = {acc[mt][nt][0] + bx, acc[mt][nt][1] + by};
            float2 v1 = {acc[mt][nt][2] + bx, acc[mt][nt][3] + by};
            *reinterpret_cast<float2*>(Cout + (size_t)row * Nt + col) = v0;
            *reinterpret_cast<float2*>(Cout + (size_t)(row + 8) * Nt + col) = v1;
        }
    }
}

#define GEMM_DSMEM_OUT (2 * (2 * MAT_A + 2 * 128 * PITCH_B))   // 81920

// =================================================================
// fp32 -> bf16 hi + fp8 h8(x) + fp8 l8((x-hi)*4096)
// =================================================================
__global__ __launch_bounds__(256) void split_hyb_k(
    const float4* __restrict__ in, uint32_t* __restrict__ hi,
    uint32_t* __restrict__ h8, uint32_t* __restrict__ l8, int n4)
{
    int i = blockIdx.x * blockDim.x + threadIdx.x;
    if (i >= n4) return;
    float4 a = in[i];
    float hx = __uint_as_float(__float_as_uint(a.x) & 0xffff0000u);
    float hy = __uint_as_float(__float_as_uint(a.y) & 0xffff0000u);
    float hz = __uint_as_float(__float_as_uint(a.z) & 0xffff0000u);
    float hw = __uint_as_float(__float_as_uint(a.w) & 0xffff0000u);
    hi[2 * i]     = pack_bf16x2(hx, hy);
    hi[2 * i + 1] = pack_bf16x2(hz, hw);
    __nv_fp8x4_e4m3 v8(a);
    h8[i] = *reinterpret_cast<uint32_t*>(&v8);
    float4 lo = make_float4((a.x - hx) * 4096.f, (a.y - hy) * 4096.f,
                            (a.z - hz) * 4096.f, (a.w - hw) * 4096.f);
    __nv_fp8x4_e4m3 vl(lo);
    l8[i] = *reinterpret_cast<uint32_t*>(&vl);
}

// =================================================================
// fp32 -> (hi, lo) bf16 split (for out-proj operands)
// =================================================================
__global__ __launch_bounds__(256) void split_bf16_k(
    const float4* __restrict__ in, __nv_bfloat162* __restrict__ hi,
    __nv_bfloat162* __restrict__ lo, int n4)
{
    int i = blockIdx.x * blockDim.x + threadIdx.x;
    if (i >= n4) return;
    float4 a = in[i];
    uint32_t h0, l0, h1, l1;
    split_pack(a.x, a.y, h0, l0);
    split_pack(a.z, a.w, h1, l1);
    reinterpret_cast<uint32_t*>(hi)[2 * i]     = h0;
    reinterpret_cast<uint32_t*>(hi)[2 * i + 1] = h1;
    reinterpret_cast<uint32_t*>(lo)[2 * i]     = l0;
    reinterpret_cast<uint32_t*>(lo)[2 * i + 1] = l1;
}

// =================================================================
// RoPE + QK-RMSNorm -> Q,K bf16 hi/lo. Q pre-scaled 0.125*log2(e).
// =================================================================
__global__ __launch_bounds__(256) void rope_rms_split(
    const float* __restrict__ qkv,
    const float* __restrict__ q_gamma, const float* __restrict__ k_gamma,
    __nv_bfloat16* __restrict__ qh, __nv_bfloat16* __restrict__ ql,
    __nv_bfloat16* __restrict__ kh, __nv_bfloat16* __restrict__ kl)
{
    int warp = (blockIdx.x * blockDim.x + threadIdx.x) >> 5;
    int lane = threadIdx.x & 31;
    if (warp >= B_ * L_ * H_) return;
    int h  = warp % H_;
    int bl = warp / H_;
    int l  = bl % L_;
    int b  = bl / L_;

    const float* base = qkv + (size_t)bl * C3_;
    const size_t orow = (((size_t)(b * H_ + h)) * L_ + l) * D_ + 2 * lane;

    float inv_freq = exp2f((float)lane * (-13.287712379549449f / 32.0f));
    float ang = (float)l * inv_freq;
    float s, c;
    sincosf(ang, &s, &c);

    {
        float t1 = base[0 * C_ + h * D_ + 2 * lane];
        float t2 = base[0 * C_ + h * D_ + 2 * lane + 1];
        float r1 = t1 * c - t2 * s;
        float r2 = t1 * s + t2 * c;
        float ss = r1 * r1 + r2 * r2;
#pragma unroll
        for (int off = 16; off > 0; off >>= 1)
            ss += __shfl_xor_sync(0xffffffffu, ss, off);
        float inv = rsqrtf(ss * (1.0f / 64.0f) + 1e-6f) * 0.18033688011112042f;
        float v0 = r1 * inv * q_gamma[h * D_ + 2 * lane];
        float v1 = r2 * inv * q_gamma[h * D_ + 2 * lane + 1];
        uint32_t hi, lo;
        split_pack(v0, v1, hi, lo);
        *reinterpret_cast<uint32_t*>(qh + orow) = hi;
        *reinterpret_cast<uint32_t*>(ql + orow) = lo;
    }
    {
        float t1 = base[1 * C_ + h * D_ + 2 * lane];
        float t2 = base[1 * C_ + h * D_ + 2 * lane + 1];
        float r1 = t1 * c - t2 * s;
        float r2 = t1 * s + t2 * c;
        float ss = r1 * r1 + r2 * r2;
#pragma unroll
        for (int off = 16; off > 0; off >>= 1)
            ss += __shfl_xor_sync(0xffffffffu, ss, off);
        float inv = rsqrtf(ss * (1.0f / 64.0f) + 1e-6f);
        float v0 = r1 * inv * k_gamma[h * D_ + 2 * lane];
        float v1 = r2 * inv * k_gamma[h * D_ + 2 * lane + 1];
        uint32_t hi, lo;
        split_pack(v0, v1, hi, lo);
        *reinterpret_cast<uint32_t*>(kh + orow) = hi;
        *reinterpret_cast<uint32_t*>(kl + orow) = lo;
    }
}

// =================================================================
// V transpose: g_qkv V-part [B,L,H,D] -> V^T bf16 hi/lo [B,H,D,L]
// =================================================================
__global__ __launch_bounds__(256) void v_transpose(
    const float* __restrict__ qkv,
    __nv_bfloat16* __restrict__ vth, __nv_bfloat16* __restrict__ vtl)
{
    __shared__ float ts[64][65];
    int tid = threadIdx.x;
    int l0 = blockIdx.x * 64;
    int bh = blockIdx.y;
    int b = bh >> 4, h = bh & 15;
    const float* src = qkv + (size_t)(b * L_ + l0) * C3_ + 2 * C_ + h * D_;
#pragma unroll
    for (int it = 0; it < 4; it++) {
        int lin = tid + it * 256;
        int i = lin >> 4, c4 = lin & 15;
        float4 v = *reinterpret_cast<const float4*>(src + (size_t)i * C3_ + c4 * 4);
        ts[i][c4 * 4 + 0] = v.x; ts[i][c4 * 4 + 1] = v.y;
        ts[i][c4 * 4 + 2] = v.z; ts[i][c4 * 4 + 3] = v.w;
    }
    __syncthreads();
#pragma unroll
    for (int it = 0; it < 8; it++) {
        int e2 = tid + it * 256;
        int j = e2 >> 5, i = (e2 & 31) * 2;
        float a = ts[i][j], bb = ts[i + 1][j];
        uint32_t hi, lo;
        split_pack(a, bb, hi, lo);
        size_t idx = ((size_t)(bh * D_ + j)) * L_ + l0 + i;
        *reinterpret_cast<uint32_t*>(vth + idx) = hi;
        *reinterpret_cast<uint32_t*>(vtl + idx) = lo;
    }
}

// =================================================================
// Flash attention on mma.sync, split-bf16 (R13, unchanged)
// =================================================================
#define AP       144
#define Q_BYTES  (128 * AP)
#define KV_MAT   (64 * AP)
#define ASTG_SZ  (4 * KV_MAT)
#define ATTN_DSMEM (2 * Q_BYTES + 2 * ASTG_SZ)

__global__ __launch_bounds__(256, 2) void attn_mma(
    const __nv_bfloat16* __restrict__ qh_g, const __nv_bfloat16* __restrict__ ql_g,
    const __nv_bfloat16* __restrict__ kh_g, const __nv_bfloat16* __restrict__ kl_g,
    const __nv_bfloat16* __restrict__ vth_g, const __nv_bfloat16* __restrict__ vtl_g,
    __nv_bfloat16* __restrict__ ath, __nv_bfloat16* __restrict__ atl)
{
    extern __shared__ char dsm[];
    const uint32_t sb  = smem_u32(dsm);
    const uint32_t QHI = sb, QLO = sb + Q_BYTES, STG = sb + 2 * Q_BYTES;

    const int tid = threadIdx.x, wid = tid >> 5, lane = tid & 31;
    const int qt = blockIdx.x, h = blockIdx.y, b = blockIdx.z;
    const size_t base = ((size_t)(b * H_ + h)) * L_ * D_;

#pragma unroll
    for (int it = 0; it < 4; it++) {
        int lin = tid + it * 256;
        int r = lin >> 3, c = lin & 7;
        uint32_t so = r * AP + c * 16;
        size_t go = base + (size_t)(qt * 128 + r) * D_ + c * 8;
        cpasync16(QHI + so, qh_g + go);
        cpasync16(QLO + so, ql_g + go);
    }
    asm volatile("cp.async.commit_group;" ::: "memory");

    auto load_kv = [&](int c, int s) {
        uint32_t st = STG + s * ASTG_SZ;
#pragma unroll
        for (int it = 0; it < 2; it++) {
            int lin = tid + it * 256;
            int r = lin >> 3, cc = lin & 7;
            uint32_t so = r * AP + cc * 16;
            size_t gk = base + (size_t)(c * 64 + r) * D_ + cc * 8;
            cpasync16(st + so,          kh_g + gk);
            cpasync16(st + KV_MAT + so, kl_g + gk);
            size_t gv = base + (size_t)r * L_ + c * 64 + cc * 8;
            cpasync16(st + 2 * KV_MAT + so, vth_g + gv);
            cpasync16(st + 3 * KV_MAT + so, vtl_g + gv);
        }
        asm volatile("cp.async.commit_group;" ::: "memory");
    };
    load_kv(0, 0);
    load_kv(1, 1);

    const int rlA = lane & 15;
    const int csA = (lane >> 4) << 3;
    const int rlB = (lane & 7) + ((lane >> 4) << 3);
    const int csB = lane & 8;

    float o[8][4];
#pragma unroll
    for (int j = 0; j < 8; j++)
#pragma unroll
        for (int t = 0; t < 4; t++) o[j][t] = 0.f;
    float m0 = -INFINITY, m1 = -INFINITY, l0 = 0.f, l1 = 0.f;

    const int NCH = L_ / 64;
    for (int c = 0; c < NCH; c++) {
        const int s = c & 1;
        if (c == NCH - 1)
            asm volatile("cp.async.wait_group 0;" ::: "memory");
        else
            asm volatile("cp.async.wait_group 1;" ::: "memory");
        __syncthreads();
        const uint32_t st = STG + s * ASTG_SZ;

        float sc[8][4];
#pragma unroll
        for (int j = 0; j < 8; j++)
#pragma unroll
            for (int t = 0; t < 4; t++) sc[j][t] = 0.f;
#pragma unroll
        for (int t = 0; t < 4; t++) {
            uint32_t qa = QHI + (uint32_t)((wid * 16 + rlA) * AP + (t * 16 + csA) * 2);
            uint32_t qhf[4], qlf[4];
            ldm4(qhf, qa);
            ldm4(qlf, qa + Q_BYTES);
#pragma unroll
            for (int p = 0; p < 4; p++) {
                uint32_t ka = st + (uint32_t)((p * 16 + rlB) * AP + (t * 16 + csB) * 2);
                uint32_t khf[4], klf[4];
                ldm4(khf, ka);
                ldm4(klf, ka + KV_MAT);
                mma_bf16(sc[2 * p],     qhf, khf);
                mma_bf16(sc[2 * p],     qhf, klf);
                mma_bf16(sc[2 * p],     qlf, khf);
                mma_bf16(sc[2 * p + 1], qhf, khf + 2);
                mma_bf16(sc[2 * p + 1], qhf, klf + 2);
                mma_bf16(sc[2 * p + 1], qlf, khf + 2);
            }
        }

        float rm0 = -INFINITY, rm1 = -INFINITY;
#pragma unroll
        for (int j = 0; j < 8; j++) {
            rm0 = fmaxf(rm0, fmaxf(sc[j][0], sc[j][1]));
            rm1 = fmaxf(rm1, fmaxf(sc[j][2], sc[j][3]));
        }
        rm0 = fmaxf(rm0, __shfl_xor_sync(0xffffffffu, rm0, 1));
        rm0 = fmaxf(rm0, __shfl_xor_sync(0xffffffffu, rm0, 2));
        rm1 = fmaxf(rm1, __shfl_xor_sync(0xffffffffu, rm1, 1));
        rm1 = fmaxf(rm1, __shfl_xor_sync(0xffffffffu, rm1, 2));
        float n0 = fmaxf(m0, rm0), n1 = fmaxf(m1, rm1);
        float cr0 = ex2f(m0 - n0), cr1 = ex2f(m1 - n1);
        m0 = n0; m1 = n1;
        float s0 = 0.f, s1 = 0.f;
#pragma unroll
        for (int j = 0; j < 8; j++) {
            sc[j][0] = ex2f(sc[j][0] - m0); s0 += sc[j][0];
            sc[j][1] = ex2f(sc[j][1] - m0); s0 += sc[j][1];
            sc[j][2] = ex2f(sc[j][2] - m1); s1 += sc[j][2];
            sc[j][3] = ex2f(sc[j][3] - m1); s1 += sc[j][3];
        }
        s0 += __shfl_xor_sync(0xffffffffu, s0, 1);
        s0 += __shfl_xor_sync(0xffffffffu, s0, 2);
        s1 += __shfl_xor_sync(0xffffffffu, s1, 1);
        s1 += __shfl_xor_sync(0xffffffffu, s1, 2);
        l0 = l0 * cr0 + s0;
        l1 = l1 * cr1 + s1;
#pragma unroll
        for (int j = 0; j < 8; j++) {
            o[j][0] *= cr0; o[j][1] *= cr0;
            o[j][2] *= cr1; o[j][3] *= cr1;
        }

#pragma unroll
        for (int t = 0; t < 4; t++) {
            uint32_t pah[4], pal[4];
            split_pack(sc[2 * t][0],     sc[2 * t][1],     pah[0], pal[0]);
            split_pack(sc[2 * t][2],     sc[2 * t][3],     pah[1], pal[1]);
            split_pack(sc[2 * t + 1][0], sc[2 * t + 1][1], pah[2], pal[2]);
            split_pack(sc[2 * t + 1][2], sc[2 * t + 1][3], pah[3], pal[3]);
#pragma unroll
            for (int p = 0; p < 4; p++) {
                uint32_t va = st + 2 * KV_MAT
                            + (uint32_t)((p * 16 + rlB) * AP + (t * 16 + csB) * 2);
                uint32_t vhf[4], vlf[4];
                ldm4(vhf, va);
                ldm4(vlf, va + KV_MAT);
                mma_bf16(o[2 * p],     pah, vhf);
                mma_bf16(o[2 * p],     pah, vlf);
                mma_bf16(o[2 * p],     pal, vhf);
                mma_bf16(o[2 * p + 1], pah, vhf + 2);
                mma_bf16(o[2 * p + 1], pah, vlf + 2);
                mma_bf16(o[2 * p + 1], pal, vhf + 2);
            }
        }
        __syncthreads();
        if (c + 2 < NCH) load_kv(c + 2, s);
    }

    float i0 = 1.f / l0, i1 = 1.f / l1;
    int ra = qt * 128 + wid * 16 + (lane >> 2);
    int colb = h * D_ + 2 * (lane & 3);
#pragma unroll
    for (int j = 0; j < 8; j++) {
        uint32_t h0, lo0, h1, lo1;
        split_pack(o[j][0] * i0, o[j][1] * i0, h0, lo0);
        split_pack(o[j][2] * i1, o[j][3] * i1, h1, lo1);
        size_t iA = (size_t)(b * L_ + ra) * C_ + colb + j * 8;
        size_t iB = iA + (size_t)8 * C_;
        *reinterpret_cast<uint32_t*>(ath + iA) = h0;
        *reinterpret_cast<uint32_t*>(atl + iA) = lo0;
        *reinterpret_cast<uint32_t*>(ath + iB) = h1;
        *reinterpret_cast<uint32_t*>(atl + iB) = lo1;
    }
}

// =================================================================
// Host launcher
// =================================================================
extern "C" void kernel_launch(void* const* d_in, const int* in_sizes, int n_in,
                              void* d_out, int out_size)
{
    const float* x       = (const float*)d_in[0];
    const float* w_qkv   = (const float*)d_in[1];
    const float* b_qkv   = (const float*)d_in[2];
    const float* w_out   = (const float*)d_in[3];
    const float* b_out   = (const float*)d_in[4];
    const float* q_gamma = (const float*)d_in[5];
    const float* k_gamma = (const float*)d_in[6];
    float* out = (float*)d_out;
    (void)in_sizes; (void)n_in; (void)out_size;

    float* qkv;
    __nv_bfloat16 *xhi, *wqhi, *wohi, *wolo, *athi, *atlo;
    uint8_t *x8, *xl8, *wq8, *wql8;
    __nv_bfloat16 *qh, *ql, *kh, *kl, *vth, *vtl;
    cudaGetSymbolAddress((void**)&qkv,  g_qkv);
    cudaGetSymbolAddress((void**)&xhi,  g_x_hi);
    cudaGetSymbolAddress((void**)&x8,   g_x_h8);
    cudaGetSymbolAddress((void**)&xl8,  g_x_l8);
    cudaGetSymbolAddress((void**)&wqhi, g_wq_hi);
    cudaGetSymbolAddress((void**)&wq8,  g_wq_h8);
    cudaGetSymbolAddress((void**)&wql8, g_wq_l8);
    cudaGetSymbolAddress((void**)&wohi, g_wo_hi);
    cudaGetSymbolAddress((void**)&wolo, g_wo_lo);
    cudaGetSymbolAddress((void**)&athi, g_at_hi);
    cudaGetSymbolAddress((void**)&atlo, g_at_lo);
    cudaGetSymbolAddress((void**)&qh,   g_qh);
    cudaGetSymbolAddress((void**)&ql,   g_ql);
    cudaGetSymbolAddress((void**)&kh,   g_kh);
    cudaGetSymbolAddress((void**)&kl,   g_kl);
    cudaGetSymbolAddress((void**)&vth,  g_vth);
    cudaGetSymbolAddress((void**)&vtl,  g_vtl);

    cudaFuncSetAttribute(gemm_qkv_hyb,
                         cudaFuncAttributeMaxDynamicSharedMemorySize, QKV_DSMEM);
    cudaFuncSetAttribute(gemm_mma<4>,
                         cudaFuncAttributeMaxDynamicSharedMemorySize, GEMM_DSMEM_OUT);
    cudaFuncSetAttribute(attn_mma,
                         cudaFuncAttributeMaxDynamicSharedMemorySize, ATTN_DSMEM);

    // 0) convert QKV operands: bf16-hi + fp8 (h8, l8*4096)
    int n4;
    n4 = BL_ * C_ / 4;
    split_hyb_k<<<n4 / 256, 256>>>((const float4*)x,
        (uint32_t*)xhi, (uint32_t*)x8, (uint32_t*)xl8, n4);
    n4 = C3_ * C_ / 4;
    split_hyb_k<<<n4 / 256, 256>>>((const float4*)w_qkv,
        (uint32_t*)wqhi, (uint32_t*)wq8, (uint32_t*)wql8, n4);
    //    out-proj weights: bf16 hi/lo
    n4 = C_ * C_ / 4;
    split_bf16_k<<<n4 / 256, 256>>>((const float4*)w_out,
        (__nv_bfloat162*)wohi, (__nv_bfloat162*)wolo, n4);

    // 1) QKV projection: hybrid bf16+fp8, tile 128x64, grid 48x32
    gemm_qkv_hyb<<<dim3(C3_ / 64, BL_ / 128), 128, QKV_DSMEM>>>(
        xhi, x8, xl8, wqhi, wq8, wql8, b_qkv, qkv, C3_);

    // 2) RoPE + RMS -> Q,K bf16 hi/lo; V^T bf16 hi/lo
    rope_rms_split<<<(B_ * L_ * H_ * 32) / 256, 256>>>(qkv, q_gamma, k_gamma,
                                                       qh, ql, kh, kl);
    v_transpose<<<dim3(L_ / 64, B_ * H_), 256>>>(qkv, vth, vtl);

    // 3) Flash attention (tensor cores) -> att hi/lo bf16 [B,L,C]
    attn_mma<<<dim3(L_ / 128, H_, B_), 256, ATTN_DSMEM>>>(
        qh, ql, kh, kl, vth, vtl, athi, atlo);

    // 4) Output projection: split att, then split-bf16 GEMM (R13)
    n4 = BL_ * C_ / 4;
    gemm_mma<4><<<dim3(C_ / 128, BL_ / 128), 128, GEMM_DSMEM_OUT>>>(
        athi, atlo, wohi, wolo, b_out, out, C_);
}

// round 15
// speedup vs baseline: 1.3953x; 1.3953x over previous
#include <cuda_runtime.h>
#include <cuda_bf16.h>
#include <math.h>
#include <stdint.h>

// Problem constants
#define B_  2
#define L_  2048
#define C_  1024
#define H_  16
#define D_  64
#define BL_ (B_*L_)      // 4096
#define C3_ (3*C_)       // 3072
#define K_  1024         // inner dim of both dense GEMMs

// ---------------- scratch (no allocation allowed) ----------------
__device__ float g_qkv[(size_t)BL_ * C3_];

__device__ __nv_bfloat16 g_x_hi [(size_t)BL_*C_];
__device__ __nv_bfloat16 g_x_lo [(size_t)BL_*C_];
__device__ __nv_bfloat16 g_wq_hi[(size_t)C3_*C_];
__device__ __nv_bfloat16 g_wq_lo[(size_t)C3_*C_];
__device__ __nv_bfloat16 g_wo_hi[(size_t)C_*C_];
__device__ __nv_bfloat16 g_wo_lo[(size_t)C_*C_];
__device__ __nv_bfloat16 g_at_hi[(size_t)BL_*C_];
__device__ __nv_bfloat16 g_at_lo[(size_t)BL_*C_];

__device__ __nv_bfloat16 g_qh [(size_t)B_*H_*L_*D_];
__device__ __nv_bfloat16 g_ql [(size_t)B_*H_*L_*D_];
__device__ __nv_bfloat16 g_kh [(size_t)B_*H_*L_*D_];
__device__ __nv_bfloat16 g_kl [(size_t)B_*H_*L_*D_];
__device__ uint16_t      g_vt16[(size_t)B_*H_*D_*L_];   // V^T in fp16

// =================================================================
// helpers
// =================================================================
__device__ __forceinline__ uint32_t smem_u32(const void* p) {
    uint32_t a;
    asm("{ .reg .u64 t; cvta.to.shared.u64 t, %1; cvt.u32.u64 %0, t; }"
        : "=r"(a) : "l"(p));
    return a;
}
__device__ __forceinline__ void cpasync16(uint32_t dst, const void* src) {
    asm volatile("cp.async.cg.shared.global [%0], [%1], 16;"
                 :: "r"(dst), "l"(src));
}
__device__ __forceinline__ void ldm4(uint32_t* r, uint32_t addr) {
    asm volatile("ldmatrix.sync.aligned.m8n8.x4.shared.b16 {%0,%1,%2,%3}, [%4];"
                 : "=r"(r[0]), "=r"(r[1]), "=r"(r[2]), "=r"(r[3]) : "r"(addr));
}
__device__ __forceinline__ void mma_bf16(float* c, const uint32_t* a,
                                         const uint32_t* b) {
    asm volatile(
        "mma.sync.aligned.m16n8k16.row.col.f32.bf16.bf16.f32 "
        "{%0,%1,%2,%3}, {%4,%5,%6,%7}, {%8,%9}, {%0,%1,%2,%3};"
        : "+f"(c[0]), "+f"(c[1]), "+f"(c[2]), "+f"(c[3])
        : "r"(a[0]), "r"(a[1]), "r"(a[2]), "r"(a[3]), "r"(b[0]), "r"(b[1]));
}
__device__ __forceinline__ void mma_f16(float* c, const uint32_t* a,
                                        const uint32_t* b) {
    asm volatile(
        "mma.sync.aligned.m16n8k16.row.col.f32.f16.f16.f32 "
        "{%0,%1,%2,%3}, {%4,%5,%6,%7}, {%8,%9}, {%0,%1,%2,%3};"
        : "+f"(c[0]), "+f"(c[1]), "+f"(c[2]), "+f"(c[3])
        : "r"(a[0]), "r"(a[1]), "r"(a[2]), "r"(a[3]), "r"(b[0]), "r"(b[1]));
}
__device__ __forceinline__ float ex2f(float x) {
    float y;
    asm("ex2.approx.f32 %0, %1;" : "=f"(y) : "f"(x));
    return y;
}
__device__ __forceinline__ uint32_t pack_bf16x2(float e, float o) {
    uint32_t r;
    asm("cvt.rn.bf16x2.f32 %0, %1, %2;" : "=r"(r) : "f"(o), "f"(e));
    return r;
}
__device__ __forceinline__ uint32_t pack_f16x2(float e, float o) {
    uint32_t r;
    asm("cvt.rn.f16x2.f32 %0, %1, %2;" : "=r"(r) : "f"(o), "f"(e));
    return r;
}
// truncation split: hi = bf16-truncate(x) (exact in bf16), lo = x - hi
__device__ __forceinline__ void split_pack(float e, float o,
                                           uint32_t& hi, uint32_t& lo) {
    float he = __uint_as_float(__float_as_uint(e) & 0xffff0000u);
    float ho = __uint_as_float(__float_as_uint(o) & 0xffff0000u);
    hi = pack_bf16x2(he, ho);
    lo = pack_bf16x2(e - he, o - ho);
}

// =================================================================
// Split-bf16 mma.sync GEMM (R13): C = A B^T + bias, templated N-tile.
// CTA 128x(32*NTP), 128 threads / 4 warps, warp 64x(16*NTP).
// =================================================================
#define PITCH_B 80
#define MAT_A   (128 * PITCH_B)

template<int NTP>
__global__ __launch_bounds__(128, 1)
void gemm_mma(const __nv_bfloat16* __restrict__ Ahi,
              const __nv_bfloat16* __restrict__ Alo,
              const __nv_bfloat16* __restrict__ Bhi,
              const __nv_bfloat16* __restrict__ Blo,
              const float* __restrict__ bias,
              float* __restrict__ Cout, int Nt)
{
    constexpr int NTILE = 32 * NTP;
    constexpr int MAT_B = NTILE * PITCH_B;
    constexpr int STG   = 2 * MAT_A + 2 * MAT_B;

    extern __shared__ char dsm[];
    const uint32_t sb = smem_u32(dsm);

    const int tid  = threadIdx.x;
    const int wid  = tid >> 5;
    const int lane = tid & 31;
    const int wm   = wid >> 1;
    const int wn   = wid & 1;
    const int row0 = blockIdx.y << 7;
    const int col0 = blockIdx.x * NTILE;

    auto load_chunk = [&](int c, int s) {
        const uint32_t st = sb + s * STG;
        const int kb = c * 32;
#pragma unroll
        for (int t = 0; t < 4; t++) {
            int lin = tid + t * 128;
            int r = lin >> 2, q = lin & 3;
            uint32_t so = (uint32_t)(r * PITCH_B + q * 16);
            size_t go = (size_t)(row0 + r) * K_ + kb + q * 8;
            cpasync16(st + so,         Ahi + go);
            cpasync16(st + MAT_A + so, Alo + go);
        }
#pragma unroll
        for (int t = 0; t < NTP; t++) {
            int lin = tid + t * 128;
            int r = lin >> 2, q = lin & 3;
            uint32_t so = (uint32_t)(r * PITCH_B + q * 16);
            size_t go = (size_t)(col0 + r) * K_ + kb + q * 8;
            cpasync16(st + 2 * MAT_A + so,         Bhi + go);
            cpasync16(st + 2 * MAT_A + MAT_B + so, Blo + go);
        }
        asm volatile("cp.async.commit_group;" ::: "memory");
    };

    float acc[4][2 * NTP][4];
#pragma unroll
    for (int i = 0; i < 4; i++)
#pragma unroll
        for (int j = 0; j < 2 * NTP; j++)
#pragma unroll
            for (int t = 0; t < 4; t++) acc[i][j][t] = 0.f;

    load_chunk(0, 0);
    load_chunk(1, 1);

    const int NCH = K_ / 32;
    const int rlA = lane & 15;
    const int csA = (lane >> 4) << 3;
    const int rlB = (lane & 7) + ((lane >> 4) << 3);
    const int csB = lane & 8;

    for (int c = 0; c < NCH; c++) {
        const int s = c & 1;
        if (c == NCH - 1)
            asm volatile("cp.async.wait_group 0;" ::: "memory");
        else
            asm volatile("cp.async.wait_group 1;" ::: "memory");
        __syncthreads();

        const uint32_t st = sb + s * STG;
#pragma unroll
        for (int kk = 0; kk < 32; kk += 16) {
            uint32_t aH[4][4], aL[4][4], bH[NTP][4], bL[NTP][4];
#pragma unroll
            for (int mt = 0; mt < 4; mt++) {
                uint32_t ad = st + (uint32_t)((wm * 64 + mt * 16 + rlA) * PITCH_B
                                              + (kk + csA) * 2);
                ldm4(aH[mt], ad);
                ldm4(aL[mt], ad + MAT_A);
            }
#pragma unroll
            for (int ntp = 0; ntp < NTP; ntp++) {
                uint32_t bd = st + 2 * MAT_A
                            + (uint32_t)((wn * (16 * NTP) + ntp * 16 + rlB) * PITCH_B
                                         + (kk + csB) * 2);
                ldm4(bH[ntp], bd);
                ldm4(bL[ntp], bd + MAT_B);
            }
#pragma unroll
            for (int mt = 0; mt < 4; mt++)
#pragma unroll
                for (int ntp = 0; ntp < NTP; ntp++) {
                    mma_bf16(acc[mt][2 * ntp],     aH[mt], bH[ntp]);
                    mma_bf16(acc[mt][2 * ntp + 1], aH[mt], bH[ntp] + 2);
                }
#pragma unroll
            for (int mt = 0; mt < 4; mt++)
#pragma unroll
                for (int ntp = 0; ntp < NTP; ntp++) {
                    mma_bf16(acc[mt][2 * ntp],     aH[mt], bL[ntp]);
                    mma_bf16(acc[mt][2 * ntp + 1], aH[mt], bL[ntp] + 2);
                }
#pragma unroll
            for (int mt = 0; mt < 4; mt++)
#pragma unroll
                for (int ntp = 0; ntp < NTP; ntp++) {
                    mma_bf16(acc[mt][2 * ntp],     aL[mt], bH[ntp]);
                    mma_bf16(acc[mt][2 * ntp + 1], aL[mt], bH[ntp] + 2);
                }
        }
        __syncthreads();
        if (c + 2 < NCH) load_chunk(c + 2, s);
    }

#pragma unroll
    for (int mt = 0; mt < 4; mt++) {
#pragma unroll
        for (int nt = 0; nt < 2 * NTP; nt++) {
            int row = row0 + wm * 64 + mt * 16 + (lane >> 2);
            int col = col0 + wn * (16 * NTP) + nt * 8 + (lane & 3) * 2;
            float bx = bias[col], by = bias[col + 1];
            float2 v0 = {acc[mt][nt][0] + bx, acc[mt][nt][1] + by};
            float2 v1 = {acc[mt][nt][2] + bx, acc[mt][nt][3] + by};
            *reinterpret_cast<float2*>(Cout + (size_t)row * Nt + col) = v0;
            *reinterpret_cast<float2*>(Cout + (size_t)(row + 8) * Nt + col) = v1;
        }
    }
}

#define GEMM_DSMEM_QKV (2 * (2 * MAT_A + 2 * 96 * PITCH_B))    // 71680
#define GEMM_DSMEM_OUT (2 * (2 * MAT_A + 2 * 128 * PITCH_B))   // 81920

// =================================================================
// fp32 -> (hi, lo) bf16 split, vectorized
// =================================================================
__global__ __launch_bounds__(256) void split_bf16_k(
    const float4* __restrict__ in, __nv_bfloat162* __restrict__ hi,
    __nv_bfloat162* __restrict__ lo, int n4)
{
    int i = blockIdx.x * blockDim.x + threadIdx.x;
    if (i >= n4) return;
    float4 a = in[i];
    uint32_t h0, l0, h1, l1;
    split_pack(a.x, a.y, h0, l0);
    split_pack(a.z, a.w, h1, l1);
    reinterpret_cast<uint32_t*>(hi)[2 * i]     = h0;
    reinterpret_cast<uint32_t*>(hi)[2 * i + 1] = h1;
    reinterpret_cast<uint32_t*>(lo)[2 * i]     = l0;
    reinterpret_cast<uint32_t*>(lo)[2 * i + 1] = l1;
}

// =================================================================
// RoPE + QK-RMSNorm -> Q,K bf16 hi/lo in [B,H,L,D].
// Q pre-scaled by 0.125*log2(e) (softmax in exp2 domain).
// =================================================================
__global__ __launch_bounds__(256) void rope_rms_split(
    const float* __restrict__ qkv,
    const float* __restrict__ q_gamma, const float* __restrict__ k_gamma,
    __nv_bfloat16* __restrict__ qh, __nv_bfloat16* __restrict__ ql,
    __nv_bfloat16* __restrict__ kh, __nv_bfloat16* __restrict__ kl)
{
    int warp = (blockIdx.x * blockDim.x + threadIdx.x) >> 5;
    int lane = threadIdx.x & 31;
    if (warp >= B_ * L_ * H_) return;
    int h  = warp % H_;
    int bl = warp / H_;
    int l  = bl % L_;
    int b  = bl / L_;

    const float* base = qkv + (size_t)bl * C3_;
    const size_t orow = (((size_t)(b * H_ + h)) * L_ + l) * D_ + 2 * lane;

    float inv_freq = exp2f((float)lane * (-13.287712379549449f / 32.0f));
    float ang = (float)l * inv_freq;
    float s, c;
    sincosf(ang, &s, &c);

    {
        float t1 = base[0 * C_ + h * D_ + 2 * lane];
        float t2 = base[0 * C_ + h * D_ + 2 * lane + 1];
        float r1 = t1 * c - t2 * s;
        float r2 = t1 * s + t2 * c;
        float ss = r1 * r1 + r2 * r2;
#pragma unroll
        for (int off = 16; off > 0; off >>= 1)
            ss += __shfl_xor_sync(0xffffffffu, ss, off);
        float inv = rsqrtf(ss * (1.0f / 64.0f) + 1e-6f) * 0.18033688011112042f;
        float v0 = r1 * inv * q_gamma[h * D_ + 2 * lane];
        float v1 = r2 * inv * q_gamma[h * D_ + 2 * lane + 1];
        uint32_t hi, lo;
        split_pack(v0, v1, hi, lo);
        *reinterpret_cast<uint32_t*>(qh + orow) = hi;
        *reinterpret_cast<uint32_t*>(ql + orow) = lo;
    }
    {
        float t1 = base[1 * C_ + h * D_ + 2 * lane];
        float t2 = base[1 * C_ + h * D_ + 2 * lane + 1];
        float r1 = t1 * c - t2 * s;
        float r2 = t1 * s + t2 * c;
        float ss = r1 * r1 + r2 * r2;
#pragma unroll
        for (int off = 16; off > 0; off >>= 1)
            ss += __shfl_xor_sync(0xffffffffu, ss, off);
        float inv = rsqrtf(ss * (1.0f / 64.0f) + 1e-6f);
        float v0 = r1 * inv * k_gamma[h * D_ + 2 * lane];
        float v1 = r2 * inv * k_gamma[h * D_ + 2 * lane + 1];
        uint32_t hi, lo;
        split_pack(v0, v1, hi, lo);
        *reinterpret_cast<uint32_t*>(kh + orow) = hi;
        *reinterpret_cast<uint32_t*>(kl + orow) = lo;
    }
}

// =================================================================
// V transpose: g_qkv V-part [B,L,H,D] -> V^T fp16 [B,H,D,L]
// =================================================================
__global__ __launch_bounds__(256) void v_transpose(
    const float* __restrict__ qkv, uint16_t* __restrict__ vt16)
{
    __shared__ float ts[64][65];
    int tid = threadIdx.x;
    int l0 = blockIdx.x * 64;
    int bh = blockIdx.y;
    int b = bh >> 4, h = bh & 15;
    const float* src = qkv + (size_t)(b * L_ + l0) * C3_ + 2 * C_ + h * D_;
#pragma unroll
    for (int it = 0; it < 4; it++) {
        int lin = tid + it * 256;
        int i = lin >> 4, c4 = lin & 15;
        float4 v = *reinterpret_cast<const float4*>(src + (size_t)i * C3_ + c4 * 4);
        ts[i][c4 * 4 + 0] = v.x; ts[i][c4 * 4 + 1] = v.y;
        ts[i][c4 * 4 + 2] = v.z; ts[i][c4 * 4 + 3] = v.w;
    }
    __syncthreads();
#pragma unroll
    for (int it = 0; it < 8; it++) {
        int e2 = tid + it * 256;
        int j = e2 >> 5, i = (e2 & 31) * 2;
        float a = ts[i][j], bb = ts[i + 1][j];
        size_t idx = ((size_t)(bh * D_ + j)) * L_ + l0 + i;
        *reinterpret_cast<uint32_t*>(vt16 + idx) = pack_f16x2(a, bb);
    }
}

// =================================================================
// Flash attention on mma.sync: S = split-bf16 3-term (exact),
// PV = single fp16 x fp16 MMA (softmax-averaged rounding cancels).
// Softmax in exp2 domain (log2e folded into Q).
// =================================================================
#define AP       144
#define Q_BYTES  (128 * AP)
#define KV_MAT   (64 * AP)
#define ASTG_SZ  (3 * KV_MAT)                       // Kh | Kl | V16
#define ATTN_DSMEM (2 * Q_BYTES + 2 * ASTG_SZ)      // 92160

__global__ __launch_bounds__(256, 2) void attn_mma(
    const __nv_bfloat16* __restrict__ qh_g, const __nv_bfloat16* __restrict__ ql_g,
    const __nv_bfloat16* __restrict__ kh_g, const __nv_bfloat16* __restrict__ kl_g,
    const uint16_t* __restrict__ vt_g,
    __nv_bfloat16* __restrict__ ath, __nv_bfloat16* __restrict__ atl)
{
    extern __shared__ char dsm[];
    const uint32_t sb  = smem_u32(dsm);
    const uint32_t QHI = sb, QLO = sb + Q_BYTES, STG = sb + 2 * Q_BYTES;

    const int tid = threadIdx.x, wid = tid >> 5, lane = tid & 31;
    const int qt = blockIdx.x, h = blockIdx.y, b = blockIdx.z;
    const size_t base = ((size_t)(b * H_ + h)) * L_ * D_;

#pragma unroll
    for (int it = 0; it < 4; it++) {
        int lin = tid + it * 256;
        int r = lin >> 3, c = lin & 7;
        uint32_t so = r * AP + c * 16;
        size_t go = base + (size_t)(qt * 128 + r) * D_ + c * 8;
        cpasync16(QHI + so, qh_g + go);
        cpasync16(QLO + so, ql_g + go);
    }
    asm volatile("cp.async.commit_group;" ::: "memory");

    auto load_kv = [&](int c, int s) {
        uint32_t st = STG + s * ASTG_SZ;
#pragma unroll
        for (int it = 0; it < 2; it++) {
            int lin = tid + it * 256;
            int r = lin >> 3, cc = lin & 7;
            uint32_t so = r * AP + cc * 16;
            size_t gk = base + (size_t)(c * 64 + r) * D_ + cc * 8;
            cpasync16(st + so,          kh_g + gk);
            cpasync16(st + KV_MAT + so, kl_g + gk);
            size_t gv = base + (size_t)r * L_ + c * 64 + cc * 8;
            cpasync16(st + 2 * KV_MAT + so, vt_g + gv);
        }
        asm volatile("cp.async.commit_group;" ::: "memory");
    };
    load_kv(0, 0);
    load_kv(1, 1);

    const int rlA = lane & 15;
    const int csA = (lane >> 4) << 3;
    const int rlB = (lane & 7) + ((lane >> 4) << 3);
    const int csB = lane & 8;

    float o[8][4];
#pragma unroll
    for (int j = 0; j < 8; j++)
#pragma unroll
        for (int t = 0; t < 4; t++) o[j][t] = 0.f;
    float m0 = -INFINITY, m1 = -INFINITY, l0 = 0.f, l1 = 0.f;

    const int NCH = L_ / 64;
    for (int c = 0; c < NCH; c++) {
        const int s = c & 1;
        if (c == NCH - 1)
            asm volatile("cp.async.wait_group 0;" ::: "memory");
        else
            asm volatile("cp.async.wait_group 1;" ::: "memory");
        __syncthreads();
        const uint32_t st = STG + s * ASTG_SZ;

        // ---- S = Q K^T, split-bf16 3-term (exact to 2^-18) ----
        float sc[8][4];
#pragma unroll
        for (int j = 0; j < 8; j++)
#pragma unroll
            for (int t = 0; t < 4; t++) sc[j][t] = 0.f;
#pragma unroll
        for (int t = 0; t < 4; t++) {
            uint32_t qa = QHI + (uint32_t)((wid * 16 + rlA) * AP + (t * 16 + csA) * 2);
            uint32_t qhf[4], qlf[4];
            ldm4(qhf, qa);
            ldm4(qlf, qa + Q_BYTES);
#pragma unroll
            for (int p = 0; p < 4; p++) {
                uint32_t ka = st + (uint32_t)((p * 16 + rlB) * AP + (t * 16 + csB) * 2);
                uint32_t khf[4], klf[4];
                ldm4(khf, ka);
                ldm4(klf, ka + KV_MAT);
                mma_bf16(sc[2 * p],     qhf, khf);
                mma_bf16(sc[2 * p],     qhf, klf);
                mma_bf16(sc[2 * p],     qlf, khf);
                mma_bf16(sc[2 * p + 1], qhf, khf + 2);
                mma_bf16(sc[2 * p + 1], qhf, klf + 2);
                mma_bf16(sc[2 * p + 1], qlf, khf + 2);
            }
        }

        // ---- online softmax in exp2 domain ----
        float rm0 = -INFINITY, rm1 = -INFINITY;
#pragma unroll
        for (int j = 0; j < 8; j++) {
            rm0 = fmaxf(rm0, fmaxf(sc[j][0], sc[j][1]));
            rm1 = fmaxf(rm1, fmaxf(sc[j][2], sc[j][3]));
        }
        rm0 = fmaxf(rm0, __shfl_xor_sync(0xffffffffu, rm0, 1));
        rm0 = fmaxf(rm0, __shfl_xor_sync(0xffffffffu, rm0, 2));
        rm1 = fmaxf(rm1, __shfl_xor_sync(0xffffffffu, rm1, 1));
        rm1 = fmaxf(rm1, __shfl_xor_sync(0xffffffffu, rm1, 2));
        float n0 = fmaxf(m0, rm0), n1 = fmaxf(m1, rm1);
        float cr0 = ex2f(m0 - n0), cr1 = ex2f(m1 - n1);
        m0 = n0; m1 = n1;
        float s0 = 0.f, s1 = 0.f;
#pragma unroll
        for (int j = 0; j < 8; j++) {
            sc[j][0] = ex2f(sc[j][0] - m0); s0 += sc[j][0];
            sc[j][1] = ex2f(sc[j][1] - m0); s0 += sc[j][1];
            sc[j][2] = ex2f(sc[j][2] - m1); s1 += sc[j][2];
            sc[j][3] = ex2f(sc[j][3] - m1); s1 += sc[j][3];
        }
        s0 += __shfl_xor_sync(0xffffffffu, s0, 1);
        s0 += __shfl_xor_sync(0xffffffffu, s0, 2);
        s1 += __shfl_xor_sync(0xffffffffu, s1, 1);
        s1 += __shfl_xor_sync(0xffffffffu, s1, 2);
        l0 = l0 * cr0 + s0;
        l1 = l1 * cr1 + s1;
#pragma unroll
        for (int j = 0; j < 8; j++) {
            o[j][0] *= cr0; o[j][1] *= cr0;
            o[j][2] *= cr1; o[j][3] *= cr1;
        }

        // ---- O += P V : single fp16 MMA (errors cancel in softmax avg) ----
#pragma unroll
        for (int t = 0; t < 4; t++) {
            uint32_t pa[4];
            pa[0] = pack_f16x2(sc[2 * t][0],     sc[2 * t][1]);
            pa[1] = pack_f16x2(sc[2 * t][2],     sc[2 * t][3]);
            pa[2] = pack_f16x2(sc[2 * t + 1][0], sc[2 * t + 1][1]);
            pa[3] = pack_f16x2(sc[2 * t + 1][2], sc[2 * t + 1][3]);
#pragma unroll
            for (int p = 0; p < 4; p++) {
                uint32_t va = st + 2 * KV_MAT
                            + (uint32_t)((p * 16 + rlB) * AP + (t * 16 + csB) * 2);
                uint32_t vhf[4];
                ldm4(vhf, va);
                mma_f16(o[2 * p],     pa, vhf);
                mma_f16(o[2 * p + 1], pa, vhf + 2);
            }
        }
        __syncthreads();
        if (c + 2 < NCH) load_kv(c + 2, s);
    }

    float i0 = 1.f / l0, i1 = 1.f / l1;
    int ra = qt * 128 + wid * 16 + (lane >> 2);
    int colb = h * D_ + 2 * (lane & 3);
#pragma unroll
    for (int j = 0; j < 8; j++) {
        uint32_t h0, lo0, h1, lo1;
        split_pack(o[j][0] * i0, o[j][1] * i0, h0, lo0);
        split_pack(o[j][2] * i1, o[j][3] * i1, h1, lo1);
        size_t iA = (size_t)(b * L_ + ra) * C_ + colb + j * 8;
        size_t iB = iA + (size_t)8 * C_;
        *reinterpret_cast<uint32_t*>(ath + iA) = h0;
        *reinterpret_cast<uint32_t*>(atl + iA) = lo0;
        *reinterpret_cast<uint32_t*>(ath + iB) = h1;
        *reinterpret_cast<uint32_t*>(atl + iB) = lo1;
    }
}

// =================================================================
// Host launcher
// =================================================================
extern "C" void kernel_launch(void* const* d_in, const int* in_sizes, int n_in,
                              void* d_out, int out_size)
{
    const float* x       = (const float*)d_in[0];
    const float* w_qkv   = (const float*)d_in[1];
    const float* b_qkv   = (const float*)d_in[2];
    const float* w_out   = (const float*)d_in[3];
    const float* b_out   = (const float*)d_in[4];
    const float* q_gamma = (const float*)d_in[5];
    const float* k_gamma = (const float*)d_in[6];
    float* out = (float*)d_out;
    (void)in_sizes; (void)n_in; (void)out_size;

    float* qkv;
    __nv_bfloat16 *xhi, *xlo, *wqhi, *wqlo, *wohi, *wolo, *athi, *atlo;
    __nv_bfloat16 *qh, *ql, *kh, *kl;
    uint16_t* vt16;
    cudaGetSymbolAddress((void**)&qkv,  g_qkv);
    cudaGetSymbolAddress((void**)&xhi,  g_x_hi);
    cudaGetSymbolAddress((void**)&xlo,  g_x_lo);
    cudaGetSymbolAddress((void**)&wqhi, g_wq_hi);
    cudaGetSymbolAddress((void**)&wqlo, g_wq_lo);
    cudaGetSymbolAddress((void**)&wohi, g_wo_hi);
    cudaGetSymbolAddress((void**)&wolo, g_wo_lo);
    cudaGetSymbolAddress((void**)&athi, g_at_hi);
    cudaGetSymbolAddress((void**)&atlo, g_at_lo);
    cudaGetSymbolAddress((void**)&qh,   g_qh);
    cudaGetSymbolAddress((void**)&ql,   g_ql);
    cudaGetSymbolAddress((void**)&kh,   g_kh);
    cudaGetSymbolAddress((void**)&kl,   g_kl);
    cudaGetSymbolAddress((void**)&vt16, g_vt16);

    cudaFuncSetAttribute(gemm_mma<3>,
                         cudaFuncAttributeMaxDynamicSharedMemorySize, GEMM_DSMEM_QKV);
    cudaFuncSetAttribute(gemm_mma<4>,
                         cudaFuncAttributeMaxDynamicSharedMemorySize, GEMM_DSMEM_OUT);
    cudaFuncSetAttribute(attn_mma,
                         cudaFuncAttributeMaxDynamicSharedMemorySize, ATTN_DSMEM);

    // 0) split inputs/weights to bf16 hi/lo
    int n4;
    n4 = BL_ * C_ / 4;
    split_bf16_k<<<n4 / 256, 256>>>((const float4*)x,
        (__nv_bfloat162*)xhi, (__nv_bfloat162*)xlo, n4);
    n4 = C3_ * C_ / 4;
    split_bf16_k<<<n4 / 256, 256>>>((const float4*)w_qkv,
        (__nv_bfloat162*)wqhi, (__nv_bfloat162*)wqlo, n4);
    n4 = C_ * C_ / 4;
    split_bf16_k<<<n4 / 256, 256>>>((const float4*)w_out,
        (__nv_bfloat162*)wohi, (__nv_bfloat162*)wolo, n4);

    // 1) QKV projection: tile 128x96 -> grid 32x32 (6.92 waves)
    gemm_mma<3><<<dim3(C3_ / 96, BL_ / 128), 128, GEMM_DSMEM_QKV>>>(
        xhi, xlo, wqhi, wqlo, b_qkv, qkv, C3_);

    // 2) RoPE + RMS -> Q,K bf16 hi/lo; V^T fp16
    rope_rms_split<<<(B_ * L_ * H_ * 32) / 256, 256>>>(qkv, q_gamma, k_gamma,
                                                       qh, ql, kh, kl);
    v_transpose<<<dim3(L_ / 64, B_ * H_), 256>>>(qkv, vt16);

    // 3) Flash attention (tensor cores) -> att hi/lo bf16 [B,L,C]
    attn_mma<<<dim3(L_ / 128, H_, B_), 256, ATTN_DSMEM>>>(
        qh, ql, kh, kl, vt16, athi, atlo);

    // 4) Output projection: tile 128x128
    gemm_mma<4><<<dim3(C_ / 128, BL_ / 128), 128, GEMM_DSMEM_OUT>>>(
        athi, atlo, wohi, wolo, b_out, out, C_);
}

// round 17
// speedup vs baseline: 1.6292x; 1.1677x over previous
#include <cuda_runtime.h>
#include <cuda_bf16.h>
#include <math.h>
#include <stdint.h>

// Problem constants
#define B_  2
#define L_  2048
#define C_  1024
#define H_  16
#define D_  64
#define BL_ (B_*L_)      // 4096
#define C3_ (3*C_)       // 3072
#define K_  1024         // inner dim of both dense GEMMs

// ---------------- scratch (no allocation allowed) ----------------
__device__ float g_qkv[(size_t)BL_ * C3_];

__device__ __nv_bfloat16 g_x_hi [(size_t)BL_*C_];
__device__ __nv_bfloat16 g_x_lo [(size_t)BL_*C_];
__device__ __nv_bfloat16 g_wq_hi[(size_t)C3_*C_];
__device__ __nv_bfloat16 g_wq_lo[(size_t)C3_*C_];
__device__ __nv_bfloat16 g_wo_hi[(size_t)C_*C_];
__device__ __nv_bfloat16 g_wo_lo[(size_t)C_*C_];
__device__ __nv_bfloat16 g_at_hi[(size_t)BL_*C_];
__device__ __nv_bfloat16 g_at_lo[(size_t)BL_*C_];

__device__ uint16_t g_q16[(size_t)B_*H_*L_*D_];   // Q fp16 (prescaled)
__device__ uint16_t g_k16[(size_t)B_*H_*L_*D_];   // K fp16
__device__ uint16_t g_vt16[(size_t)B_*H_*D_*L_];  // V^T fp16

// =================================================================
// helpers
// =================================================================
__device__ __forceinline__ uint32_t smem_u32(const void* p) {
    uint32_t a;
    asm("{ .reg .u64 t; cvta.to.shared.u64 t, %1; cvt.u32.u64 %0, t; }"
        : "=r"(a) : "l"(p));
    return a;
}
__device__ __forceinline__ void cpasync16(uint32_t dst, const void* src) {
    asm volatile("cp.async.cg.shared.global [%0], [%1], 16;"
                 :: "r"(dst), "l"(src));
}
__device__ __forceinline__ void ldm4(uint32_t* r, uint32_t addr) {
    asm volatile("ldmatrix.sync.aligned.m8n8.x4.shared.b16 {%0,%1,%2,%3}, [%4];"
                 : "=r"(r[0]), "=r"(r[1]), "=r"(r[2]), "=r"(r[3]) : "r"(addr));
}
__device__ __forceinline__ void mma_bf16(float* c, const uint32_t* a,
                                         const uint32_t* b) {
    asm volatile(
        "mma.sync.aligned.m16n8k16.row.col.f32.bf16.bf16.f32 "
        "{%0,%1,%2,%3}, {%4,%5,%6,%7}, {%8,%9}, {%0,%1,%2,%3};"
        : "+f"(c[0]), "+f"(c[1]), "+f"(c[2]), "+f"(c[3])
        : "r"(a[0]), "r"(a[1]), "r"(a[2]), "r"(a[3]), "r"(b[0]), "r"(b[1]));
}
__device__ __forceinline__ void mma_f16(float* c, const uint32_t* a,
                                        const uint32_t* b) {
    asm volatile(
        "mma.sync.aligned.m16n8k16.row.col.f32.f16.f16.f32 "
        "{%0,%1,%2,%3}, {%4,%5,%6,%7}, {%8,%9}, {%0,%1,%2,%3};"
        : "+f"(c[0]), "+f"(c[1]), "+f"(c[2]), "+f"(c[3])
        : "r"(a[0]), "r"(a[1]), "r"(a[2]), "r"(a[3]), "r"(b[0]), "r"(b[1]));
}
__device__ __forceinline__ float ex2f(float x) {
    float y;
    asm("ex2.approx.f32 %0, %1;" : "=f"(y) : "f"(x));
    return y;
}
__device__ __forceinline__ uint32_t pack_bf16x2(float e, float o) {
    uint32_t r;
    asm("cvt.rn.bf16x2.f32 %0, %1, %2;" : "=r"(r) : "f"(o), "f"(e));
    return r;
}
__device__ __forceinline__ uint32_t pack_f16x2(float e, float o) {
    uint32_t r;
    asm("cvt.rn.f16x2.f32 %0, %1, %2;" : "=r"(r) : "f"(o), "f"(e));
    return r;
}
// truncation split: hi = bf16-truncate(x) (exact in bf16), lo = x - hi
__device__ __forceinline__ void split_pack(float e, float o,
                                           uint32_t& hi, uint32_t& lo) {
    float he = __uint_as_float(__float_as_uint(e) & 0xffff0000u);
    float ho = __uint_as_float(__float_as_uint(o) & 0xffff0000u);
    hi = pack_bf16x2(he, ho);
    lo = pack_bf16x2(e - he, o - ho);
}

// =================================================================
// Split-bf16 mma.sync GEMM (R13): C = A B^T + bias, templated N-tile.
// =================================================================
#define PITCH_B 80
#define MAT_A   (128 * PITCH_B)

template<int NTP>
__global__ __launch_bounds__(128, 1)
void gemm_mma(const __nv_bfloat16* __restrict__ Ahi,
              const __nv_bfloat16* __restrict__ Alo,
              const __nv_bfloat16* __restrict__ Bhi,
              const __nv_bfloat16* __restrict__ Blo,
              const float* __restrict__ bias,
              float* __restrict__ Cout, int Nt)
{
    constexpr int NTILE = 32 * NTP;
    constexpr int MAT_B = NTILE * PITCH_B;
    constexpr int STG   = 2 * MAT_A + 2 * MAT_B;

    extern __shared__ char dsm[];
    const uint32_t sb = smem_u32(dsm);

    const int tid  = threadIdx.x;
    const int wid  = tid >> 5;
    const int lane = tid & 31;
    const int wm   = wid >> 1;
    const int wn   = wid & 1;
    const int row0 = blockIdx.y << 7;
    const int col0 = blockIdx.x * NTILE;

    auto load_chunk = [&](int c, int s) {
        const uint32_t st = sb + s * STG;
        const int kb = c * 32;
#pragma unroll
        for (int t = 0; t < 4; t++) {
            int lin = tid + t * 128;
            int r = lin >> 2, q = lin & 3;
            uint32_t so = (uint32_t)(r * PITCH_B + q * 16);
            size_t go = (size_t)(row0 + r) * K_ + kb + q * 8;
            cpasync16(st + so,         Ahi + go);
            cpasync16(st + MAT_A + so, Alo + go);
        }
#pragma unroll
        for (int t = 0; t < NTP; t++) {
            int lin = tid + t * 128;
            int r = lin >> 2, q = lin & 3;
            uint32_t so = (uint32_t)(r * PITCH_B + q * 16);
            size_t go = (size_t)(col0 + r) * K_ + kb + q * 8;
            cpasync16(st + 2 * MAT_A + so,         Bhi + go);
            cpasync16(st + 2 * MAT_A + MAT_B + so, Blo + go);
        }
        asm volatile("cp.async.commit_group;" ::: "memory");
    };

    float acc[4][2 * NTP][4];
#pragma unroll
    for (int i = 0; i < 4; i++)
#pragma unroll
        for (int j = 0; j < 2 * NTP; j++)
#pragma unroll
            for (int t = 0; t < 4; t++) acc[i][j][t] = 0.f;

    load_chunk(0, 0);
    load_chunk(1, 1);

    const int NCH = K_ / 32;
    const int rlA = lane & 15;
    const int csA = (lane >> 4) << 3;
    const int rlB = (lane & 7) + ((lane >> 4) << 3);
    const int csB = lane & 8;

    for (int c = 0; c < NCH; c++) {
        const int s = c & 1;
        if (c == NCH - 1)
            asm volatile("cp.async.wait_group 0;" ::: "memory");
        else
            asm volatile("cp.async.wait_group 1;" ::: "memory");
        __syncthreads();

        const uint32_t st = sb + s * STG;
#pragma unroll
        for (int kk = 0; kk < 32; kk += 16) {
            uint32_t aH[4][4], aL[4][4], bH[NTP][4], bL[NTP][4];
#pragma unroll
            for (int mt = 0; mt < 4; mt++) {
                uint32_t ad = st + (uint32_t)((wm * 64 + mt * 16 + rlA) * PITCH_B
                                              + (kk + csA) * 2);
                ldm4(aH[mt], ad);
                ldm4(aL[mt], ad + MAT_A);
            }
#pragma unroll
            for (int ntp = 0; ntp < NTP; ntp++) {
                uint32_t bd = st + 2 * MAT_A
                            + (uint32_t)((wn * (16 * NTP) + ntp * 16 + rlB) * PITCH_B
                                         + (kk + csB) * 2);
                ldm4(bH[ntp], bd);
                ldm4(bL[ntp], bd + MAT_B);
            }
#pragma unroll
            for (int mt = 0; mt < 4; mt++)
#pragma unroll
                for (int ntp = 0; ntp < NTP; ntp++) {
                    mma_bf16(acc[mt][2 * ntp],     aH[mt], bH[ntp]);
                    mma_bf16(acc[mt][2 * ntp + 1], aH[mt], bH[ntp] + 2);
                }
#pragma unroll
            for (int mt = 0; mt < 4; mt++)
#pragma unroll
                for (int ntp = 0; ntp < NTP; ntp++) {
                    mma_bf16(acc[mt][2 * ntp],     aH[mt], bL[ntp]);
                    mma_bf16(acc[mt][2 * ntp + 1], aH[mt], bL[ntp] + 2);
                }
#pragma unroll
            for (int mt = 0; mt < 4; mt++)
#pragma unroll
                for (int ntp = 0; ntp < NTP; ntp++) {
                    mma_bf16(acc[mt][2 * ntp],     aL[mt], bH[ntp]);
                    mma_bf16(acc[mt][2 * ntp + 1], aL[mt], bH[ntp] + 2);
                }
        }
        __syncthreads();
        if (c + 2 < NCH) load_chunk(c + 2, s);
    }

#pragma unroll
    for (int mt = 0; mt < 4; mt++) {
#pragma unroll
        for (int nt = 0; nt < 2 * NTP; nt++) {
            int row = row0 + wm * 64 + mt * 16 + (lane >> 2);
            int col = col0 + wn * (16 * NTP) + nt * 8 + (lane & 3) * 2;
            float bx = bias[col], by = bias[col + 1];
            float2 v0 = {acc[mt][nt][0] + bx, acc[mt][nt][1] + by};
            float2 v1 = {acc[mt][nt][2] + bx, acc[mt][nt][3] + by};
            *reinterpret_cast<float2*>(Cout + (size_t)row * Nt + col) = v0;
            *reinterpret_cast<float2*>(Cout + (size_t)(row + 8) * Nt + col) = v1;
        }
    }
}

#define GEMM_DSMEM_QKV (2 * (2 * MAT_A + 2 * 96 * PITCH_B))    // 71680
#define GEMM_DSMEM_OUT (2 * (2 * MAT_A + 2 * 128 * PITCH_B))   // 81920

// =================================================================
// fp32 -> (hi, lo) bf16 split, vectorized
// =================================================================
__global__ __launch_bounds__(256) void split_bf16_k(
    const float4* __restrict__ in, __nv_bfloat162* __restrict__ hi,
    __nv_bfloat162* __restrict__ lo, int n4)
{
    int i = blockIdx.x * blockDim.x + threadIdx.x;
    if (i >= n4) return;
    float4 a = in[i];
    uint32_t h0, l0, h1, l1;
    split_pack(a.x, a.y, h0, l0);
    split_pack(a.z, a.w, h1, l1);
    reinterpret_cast<uint32_t*>(hi)[2 * i]     = h0;
    reinterpret_cast<uint32_t*>(hi)[2 * i + 1] = h1;
    reinterpret_cast<uint32_t*>(lo)[2 * i]     = l0;
    reinterpret_cast<uint32_t*>(lo)[2 * i + 1] = l1;
}

// =================================================================
// RoPE + QK-RMSNorm -> Q,K fp16 in [B,H,L,D].
// Q pre-scaled by 0.125*log2(e) (softmax in exp2 domain).
// =================================================================
__global__ __launch_bounds__(256) void rope_rms_split(
    const float* __restrict__ qkv,
    const float* __restrict__ q_gamma, const float* __restrict__ k_gamma,
    uint16_t* __restrict__ q16, uint16_t* __restrict__ k16)
{
    int warp = (blockIdx.x * blockDim.x + threadIdx.x) >> 5;
    int lane = threadIdx.x & 31;
    if (warp >= B_ * L_ * H_) return;
    int h  = warp % H_;
    int bl = warp / H_;
    int l  = bl % L_;
    int b  = bl / L_;

    const float* base = qkv + (size_t)bl * C3_;
    const size_t orow = (((size_t)(b * H_ + h)) * L_ + l) * D_ + 2 * lane;

    float inv_freq = exp2f((float)lane * (-13.287712379549449f / 32.0f));
    float ang = (float)l * inv_freq;
    float s, c;
    sincosf(ang, &s, &c);

    {
        float t1 = base[0 * C_ + h * D_ + 2 * lane];
        float t2 = base[0 * C_ + h * D_ + 2 * lane + 1];
        float r1 = t1 * c - t2 * s;
        float r2 = t1 * s + t2 * c;
        float ss = r1 * r1 + r2 * r2;
#pragma unroll
        for (int off = 16; off > 0; off >>= 1)
            ss += __shfl_xor_sync(0xffffffffu, ss, off);
        float inv = rsqrtf(ss * (1.0f / 64.0f) + 1e-6f) * 0.18033688011112042f;
        float v0 = r1 * inv * q_gamma[h * D_ + 2 * lane];
        float v1 = r2 * inv * q_gamma[h * D_ + 2 * lane + 1];
        *reinterpret_cast<uint32_t*>(q16 + orow) = pack_f16x2(v0, v1);
    }
    {
        float t1 = base[1 * C_ + h * D_ + 2 * lane];
        float t2 = base[1 * C_ + h * D_ + 2 * lane + 1];
        float r1 = t1 * c - t2 * s;
        float r2 = t1 * s + t2 * c;
        float ss = r1 * r1 + r2 * r2;
#pragma unroll
        for (int off = 16; off > 0; off >>= 1)
            ss += __shfl_xor_sync(0xffffffffu, ss, off);
        float inv = rsqrtf(ss * (1.0f / 64.0f) + 1e-6f);
        float v0 = r1 * inv * k_gamma[h * D_ + 2 * lane];
        float v1 = r2 * inv * k_gamma[h * D_ + 2 * lane + 1];
        *reinterpret_cast<uint32_t*>(k16 + orow) = pack_f16x2(v0, v1);
    }
}

// =================================================================
// V transpose: g_qkv V-part [B,L,H,D] -> V^T fp16 [B,H,D,L]
// =================================================================
__global__ __launch_bounds__(256) void v_transpose(
    const float* __restrict__ qkv, uint16_t* __restrict__ vt16)
{
    __shared__ float ts[64][65];
    int tid = threadIdx.x;
    int l0 = blockIdx.x * 64;
    int bh = blockIdx.y;
    int b = bh >> 4, h = bh & 15;
    const float* src = qkv + (size_t)(b * L_ + l0) * C3_ + 2 * C_ + h * D_;
#pragma unroll
    for (int it = 0; it < 4; it++) {
        int lin = tid + it * 256;
        int i = lin >> 4, c4 = lin & 15;
        float4 v = *reinterpret_cast<const float4*>(src + (size_t)i * C3_ + c4 * 4);
        ts[i][c4 * 4 + 0] = v.x; ts[i][c4 * 4 + 1] = v.y;
        ts[i][c4 * 4 + 2] = v.z; ts[i][c4 * 4 + 3] = v.w;
    }
    __syncthreads();
#pragma unroll
    for (int it = 0; it < 8; it++) {
        int e2 = tid + it * 256;
        int j = e2 >> 5, i = (e2 & 31) * 2;
        float a = ts[i][j], bb = ts[i + 1][j];
        size_t idx = ((size_t)(bh * D_ + j)) * L_ + l0 + i;
        *reinterpret_cast<uint32_t*>(vt16 + idx) = pack_f16x2(a, bb);
    }
}

// =================================================================
// Flash attention on mma.sync: S = single fp16 MMA (Q,K fp16, 2^-11
// rounding cancels in softmax avg), PV = single fp16 MMA.
// Softmax in exp2 domain (log2e folded into Q).
// =================================================================
#define AP       144
#define Q_BYTES  (128 * AP)                         // 18432
#define KV_MAT   (64 * AP)                          // 9216
#define ASTG_SZ  (2 * KV_MAT)                       // K | V
#define ATTN_DSMEM (Q_BYTES + 2 * ASTG_SZ)          // 55296

__global__ __launch_bounds__(256, 2) void attn_mma(
    const uint16_t* __restrict__ q_g, const uint16_t* __restrict__ k_g,
    const uint16_t* __restrict__ vt_g,
    __nv_bfloat16* __restrict__ ath, __nv_bfloat16* __restrict__ atl)
{
    extern __shared__ char dsm[];
    const uint32_t sb  = smem_u32(dsm);
    const uint32_t QS = sb, STG = sb + Q_BYTES;

    const int tid = threadIdx.x, wid = tid >> 5, lane = tid & 31;
    const int qt = blockIdx.x, h = blockIdx.y, b = blockIdx.z;
    const size_t base = ((size_t)(b * H_ + h)) * L_ * D_;

#pragma unroll
    for (int it = 0; it < 4; it++) {
        int lin = tid + it * 256;
        int r = lin >> 3, c = lin & 7;
        uint32_t so = r * AP + c * 16;
        size_t go = base + (size_t)(qt * 128 + r) * D_ + c * 8;
        cpasync16(QS + so, q_g + go);
    }
    asm volatile("cp.async.commit_group;" ::: "memory");

    auto load_kv = [&](int c, int s) {
        uint32_t st = STG + s * ASTG_SZ;
#pragma unroll
        for (int it = 0; it < 2; it++) {
            int lin = tid + it * 256;
            int r = lin >> 3, cc = lin & 7;
            uint32_t so = r * AP + cc * 16;
            size_t gk = base + (size_t)(c * 64 + r) * D_ + cc * 8;
            cpasync16(st + so, k_g + gk);
            size_t gv = base + (size_t)r * L_ + c * 64 + cc * 8;
            cpasync16(st + KV_MAT + so, vt_g + gv);
        }
        asm volatile("cp.async.commit_group;" ::: "memory");
    };
    load_kv(0, 0);
    load_kv(1, 1);

    const int rlA = lane & 15;
    const int csA = (lane >> 4) << 3;
    const int rlB = (lane & 7) + ((lane >> 4) << 3);
    const int csB = lane & 8;

    float o[8][4];
#pragma unroll
    for (int j = 0; j < 8; j++)
#pragma unroll
        for (int t = 0; t < 4; t++) o[j][t] = 0.f;
    float m0 = -INFINITY, m1 = -INFINITY, l0 = 0.f, l1 = 0.f;

    const int NCH = L_ / 64;
    for (int c = 0; c < NCH; c++) {
        const int s = c & 1;
        if (c == NCH - 1)
            asm volatile("cp.async.wait_group 0;" ::: "memory");
        else
            asm volatile("cp.async.wait_group 1;" ::: "memory");
        __syncthreads();
        const uint32_t st = STG + s * ASTG_SZ;

        // ---- S = Q K^T, single fp16 MMA per fragment ----
        float sc[8][4];
#pragma unroll
        for (int j = 0; j < 8; j++)
#pragma unroll
            for (int t = 0; t < 4; t++) sc[j][t] = 0.f;
#pragma unroll
        for (int t = 0; t < 4; t++) {
            uint32_t qa = QS + (uint32_t)((wid * 16 + rlA) * AP + (t * 16 + csA) * 2);
            uint32_t qf[4];
            ldm4(qf, qa);
#pragma unroll
            for (int p = 0; p < 4; p++) {
                uint32_t ka = st + (uint32_t)((p * 16 + rlB) * AP + (t * 16 + csB) * 2);
                uint32_t kf[4];
                ldm4(kf, ka);
                mma_f16(sc[2 * p],     qf, kf);
                mma_f16(sc[2 * p + 1], qf, kf + 2);
            }
        }

        // ---- online softmax in exp2 domain ----
        float rm0 = -INFINITY, rm1 = -INFINITY;
#pragma unroll
        for (int j = 0; j < 8; j++) {
            rm0 = fmaxf(rm0, fmaxf(sc[j][0], sc[j][1]));
            rm1 = fmaxf(rm1, fmaxf(sc[j][2], sc[j][3]));
        }
        rm0 = fmaxf(rm0, __shfl_xor_sync(0xffffffffu, rm0, 1));
        rm0 = fmaxf(rm0, __shfl_xor_sync(0xffffffffu, rm0, 2));
        rm1 = fmaxf(rm1, __shfl_xor_sync(0xffffffffu, rm1, 1));
        rm1 = fmaxf(rm1, __shfl_xor_sync(0xffffffffu, rm1, 2));
        float n0 = fmaxf(m0, rm0), n1 = fmaxf(m1, rm1);
        float cr0 = ex2f(m0 - n0), cr1 = ex2f(m1 - n1);
        m0 = n0; m1 = n1;
        float s0 = 0.f, s1 = 0.f;
#pragma unroll
        for (int j = 0; j < 8; j++) {
            sc[j][0] = ex2f(sc[j][0] - m0); s0 += sc[j][0];
            sc[j][1] = ex2f(sc[j][1] - m0); s0 += sc[j][1];
            sc[j][2] = ex2f(sc[j][2] - m1); s1 += sc[j][2];
            sc[j][3] = ex2f(sc[j][3] - m1); s1 += sc[j][3];
        }
        s0 += __shfl_xor_sync(0xffffffffu, s0, 1);
        s0 += __shfl_xor_sync(0xffffffffu, s0, 2);
        s1 += __shfl_xor_sync(0xffffffffu, s1, 1);
        s1 += __shfl_xor_sync(0xffffffffu, s1, 2);
        l0 = l0 * cr0 + s0;
        l1 = l1 * cr1 + s1;
#pragma unroll
        for (int j = 0; j < 8; j++) {
            o[j][0] *= cr0; o[j][1] *= cr0;
            o[j][2] *= cr1; o[j][3] *= cr1;
        }

        // ---- O += P V : single fp16 MMA ----
#pragma unroll
        for (int t = 0; t < 4; t++) {
            uint32_t pa[4];
            pa[0] = pack_f16x2(sc[2 * t][0],     sc[2 * t][1]);
            pa[1] = pack_f16x2(sc[2 * t][2],     sc[2 * t][3]);
            pa[2] = pack_f16x2(sc[2 * t + 1][0], sc[2 * t + 1][1]);
            pa[3] = pack_f16x2(sc[2 * t + 1][2], sc[2 * t + 1][3]);
#pragma unroll
            for (int p = 0; p < 4; p++) {
                uint32_t va = st + KV_MAT
                            + (uint32_t)((p * 16 + rlB) * AP + (t * 16 + csB) * 2);
                uint32_t vhf[4];
                ldm4(vhf, va);
                mma_f16(o[2 * p],     pa, vhf);
                mma_f16(o[2 * p + 1], pa, vhf + 2);
            }
        }
        __syncthreads();
        if (c + 2 < NCH) load_kv(c + 2, s);
    }

    float i0 = 1.f / l0, i1 = 1.f / l1;
    int ra = qt * 128 + wid * 16 + (lane >> 2);
    int colb = h * D_ + 2 * (lane & 3);
#pragma unroll
    for (int j = 0; j < 8; j++) {
        uint32_t h0, lo0, h1, lo1;
        split_pack(o[j][0] * i0, o[j][1] * i0, h0, lo0);
        split_pack(o[j][2] * i1, o[j][3] * i1, h1, lo1);
        size_t iA = (size_t)(b * L_ + ra) * C_ + colb + j * 8;
        size_t iB = iA + (size_t)8 * C_;
        *reinterpret_cast<uint32_t*>(ath + iA) = h0;
        *reinterpret_cast<uint32_t*>(atl + iA) = lo0;
        *reinterpret_cast<uint32_t*>(ath + iB) = h1;
        *reinterpret_cast<uint32_t*>(atl + iB) = lo1;
    }
}

// =================================================================
// Host launcher
// =================================================================
extern "C" void kernel_launch(void* const* d_in, const int* in_sizes, int n_in,
                              void* d_out, int out_size)
{
    const float* x       = (const float*)d_in[0];
    const float* w_qkv   = (const float*)d_in[1];
    const float* b_qkv   = (const float*)d_in[2];
    const float* w_out   = (const float*)d_in[3];
    const float* b_out   = (const float*)d_in[4];
    const float* q_gamma = (const float*)d_in[5];
    const float* k_gamma = (const float*)d_in[6];
    float* out = (float*)d_out;
    (void)in_sizes; (void)n_in; (void)out_size;

    float* qkv;
    __nv_bfloat16 *xhi, *xlo, *wqhi, *wqlo, *wohi, *wolo, *athi, *atlo;
    uint16_t *q16, *k16, *vt16;
    cudaGetSymbolAddress((void**)&qkv,  g_qkv);
    cudaGetSymbolAddress((void**)&xhi,  g_x_hi);
    cudaGetSymbolAddress((void**)&xlo,  g_x_lo);
    cudaGetSymbolAddress((void**)&wqhi, g_wq_hi);
    cudaGetSymbolAddress((void**)&wqlo, g_wq_lo);
    cudaGetSymbolAddress((void**)&wohi, g_wo_hi);
    cudaGetSymbolAddress((void**)&wolo, g_wo_lo);
    cudaGetSymbolAddress((void**)&athi, g_at_hi);
    cudaGetSymbolAddress((void**)&atlo, g_at_lo);
    cudaGetSymbolAddress((void**)&q16,  g_q16);
    cudaGetSymbolAddress((void**)&k16,  g_k16);
    cudaGetSymbolAddress((void**)&vt16, g_vt16);

    cudaFuncSetAttribute(gemm_mma<3>,
                         cudaFuncAttributeMaxDynamicSharedMemorySize, GEMM_DSMEM_QKV);
    cudaFuncSetAttribute(gemm_mma<4>,
                         cudaFuncAttributeMaxDynamicSharedMemorySize, GEMM_DSMEM_OUT);
    cudaFuncSetAttribute(attn_mma,
                         cudaFuncAttributeMaxDynamicSharedMemorySize, ATTN_DSMEM);

    // 0) split inputs/weights to bf16 hi/lo
    int n4;
    n4 = BL_ * C_ / 4;
    split_bf16_k<<<n4 / 256, 256>>>((const float4*)x,
        (__nv_bfloat162*)xhi, (__nv_bfloat162*)xlo, n4);
    n4 = C3_ * C_ / 4;
    split_bf16_k<<<n4 / 256, 256>>>((const float4*)w_qkv,
        (__nv_bfloat162*)wqhi, (__nv_bfloat162*)wqlo, n4);
    n4 = C_ * C_ / 4;
    split_bf16_k<<<n4 / 256, 256>>>((const float4*)w_out,
        (__nv_bfloat162*)wohi, (__nv_bfloat162*)wolo, n4);

    // 1) QKV projection: tile 128x96 -> grid 32x32 (6.92 waves)
    gemm_mma<3><<<dim3(C3_ / 96, BL_ / 128), 128, GEMM_DSMEM_QKV>>>(
        xhi, xlo, wqhi, wqlo, b_qkv, qkv, C3_);

    // 2) RoPE + RMS -> Q,K fp16; V^T fp16
    rope_rms_split<<<(B_ * L_ * H_ * 32) / 256, 256>>>(qkv, q_gamma, k_gamma,
                                                       q16, k16);
    v_transpose<<<dim3(L_ / 64, B_ * H_), 256>>>(qkv, vt16);

    // 3) Flash attention (tensor cores) -> att hi/lo bf16 [B,L,C]
    attn_mma<<<dim3(L_ / 128, H_, B_), 256, ATTN_DSMEM>>>(
        q16, k16, vt16, athi, atlo);

    // 4) Output projection: tile 128x128
    gemm_mma<4><<<dim3(C_ / 128, BL_ / 128), 128, GEMM_DSMEM_OUT>>>(
        athi, atlo, wohi, wolo, b_out, out, C_);
}